// round 10
// baseline (speedup 1.0000x reference)
#include <cuda_runtime.h>
#include <cuda_fp16.h>
#include <cstdint>

#define FEAT      2048
#define NPROBE    64
#define NGALLERY  256
#define NROWS     16384           // NPROBE * NGALLERY
#define NCLS      751
#define NPAD      768
#define BN_EPS    1e-5f

#define BM        128
#define BN        64
#define BK        64
#define KITERS    (FEAT / BK)     // 32
#define THREADS   256             // 8 warps (4M x 2N), warp tile 32x32
#define WSCALE    64.0f
#define WSCALE_INV (1.0f / 64.0f)

// 3-stage smem pipeline: per stage A 16KB + B 8KB = 24KB -> 72KB, 3 CTAs/SM
#define STAGE_BYTES 24576
#define NSTAGES     3
#define SMEM_TOTAL  (NSTAGES * STAGE_BYTES)   // 73728 B

#define EPI_STRIDE  68            // fp32 words

// ---------------- device scratch ----------------
__device__ __align__(16) float g_scale[FEAT];
__device__ __align__(16) float g_mean[FEAT];
__device__ __align__(16) float g_cconst[NPAD];
__device__ __align__(16) __half g_W16[NPAD * FEAT];          // 3 MB
__device__ __align__(16) __half g_A16[(size_t)NROWS * FEAT]; // 64 MB

// ---------------- helpers ----------------
__device__ __forceinline__ uint32_t smem_u32(const void* p) {
    uint32_t a;
    asm("{ .reg .u64 t; cvta.to.shared.u64 t, %1; cvt.u32.u64 %0, t; }"
        : "=r"(a) : "l"(p));
    return a;
}
__device__ __forceinline__ uint32_t sw128(uint32_t off) {
    return off ^ ((off >> 3) & 0x70);
}
__device__ __forceinline__ void cp16cg(uint32_t dst, const void* src) {
    asm volatile("cp.async.cg.shared.global [%0], [%1], 16;"
                 :: "r"(dst), "l"(src) : "memory");
}
__device__ __forceinline__ void cp16ca(uint32_t dst, const void* src) {
    asm volatile("cp.async.ca.shared.global [%0], [%1], 16;"
                 :: "r"(dst), "l"(src) : "memory");
}
#define CP_COMMIT() asm volatile("cp.async.commit_group;" ::: "memory")
#define CP_WAIT2()  asm volatile("cp.async.wait_group 2;" ::: "memory")

__device__ __forceinline__ void ldsm4(uint32_t* r, uint32_t addr) {
    asm volatile("ldmatrix.sync.aligned.m8n8.x4.shared.b16 {%0,%1,%2,%3}, [%4];"
                 : "=r"(r[0]), "=r"(r[1]), "=r"(r[2]), "=r"(r[3]) : "r"(addr));
}
__device__ __forceinline__ void mma16816(float* c, const uint32_t* a,
                                         const uint32_t* b) {
    asm volatile(
        "mma.sync.aligned.m16n8k16.row.col.f32.f16.f16.f32 "
        "{%0,%1,%2,%3}, {%4,%5,%6,%7}, {%8,%9}, {%0,%1,%2,%3};"
        : "+f"(c[0]), "+f"(c[1]), "+f"(c[2]), "+f"(c[3])
        : "r"(a[0]), "r"(a[1]), "r"(a[2]), "r"(a[3]), "r"(b[0]), "r"(b[1]));
}

// ---------------- kernel 1: BN stats in one pass ----------------
// 8 blocks x 256 threads; each thread owns one feature over all 320 rows.
__global__ void stats_kernel(const float* __restrict__ probe,
                             const float* __restrict__ gallery,
                             const float* __restrict__ gamma) {
    const int f = blockIdx.x * 256 + threadIdx.x;
    float sp1 = 0.f, sp2 = 0.f, sp3 = 0.f, sp4 = 0.f;
    #pragma unroll 8
    for (int r = 0; r < NPROBE; r++) {
        float v = probe[(size_t)r * FEAT + f];
        float v2 = v * v;
        sp1 += v; sp2 += v2; sp3 += v2 * v; sp4 += v2 * v2;
    }
    float sg1 = 0.f, sg2 = 0.f, sg3 = 0.f, sg4 = 0.f;
    #pragma unroll 8
    for (int r = 0; r < NGALLERY; r++) {
        float v = gallery[(size_t)r * FEAT + f];
        float v2 = v * v;
        sg1 += v; sg2 += v2; sg3 += v2 * v; sg4 += v2 * v2;
    }
    const float ip = 1.f / NPROBE, ig = 1.f / NGALLERY;
    float mp1 = sp1 * ip, mp2 = sp2 * ip, mp3 = sp3 * ip, mp4 = sp4 * ip;
    float mg1 = sg1 * ig, mg2 = sg2 * ig, mg3 = sg3 * ig, mg4 = sg4 * ig;
    // exact identities: the BN batch is the full (i,j) cartesian product
    float mean = mp2 + mg2 - 2.f * mp1 * mg1;
    float ed2  = mp4 - 4.f * mp3 * mg1 + 6.f * mp2 * mg2 - 4.f * mp1 * mg3 + mg4;
    float var  = ed2 - mean * mean;
    g_mean[f]  = mean;
    g_scale[f] = gamma[f] * rsqrtf(var + BN_EPS);
}

// ---------------- kernel 2: fused A16 build + W prep ----------------
__global__ void fused_prep_kernel(const float* __restrict__ probe,
                                  const float* __restrict__ gallery,
                                  const float* __restrict__ W,
                                  const float* __restrict__ beta,
                                  const float* __restrict__ bias) {
    const int bx = blockIdx.x;
    const int tid = threadIdx.x;
    if (bx < 1024) {
        const int i = bx >> 4;
        const int jc = bx & 15;
        const int f0 = tid * 8;
        float4 p0 = *(const float4*)&probe[(size_t)i * FEAT + f0];
        float4 p1 = *(const float4*)&probe[(size_t)i * FEAT + f0 + 4];
        float4 m0 = *(const float4*)&g_mean[f0];
        float4 m1 = *(const float4*)&g_mean[f0 + 4];
        #pragma unroll 4
        for (int jj = 0; jj < 16; jj++) {
            const int j = jc * 16 + jj;
            float4 gv0 = *(const float4*)&gallery[(size_t)j * FEAT + f0];
            float4 gv1 = *(const float4*)&gallery[(size_t)j * FEAT + f0 + 4];
            float d[8];
            d[0] = p0.x - gv0.x; d[0] = d[0] * d[0] - m0.x;
            d[1] = p0.y - gv0.y; d[1] = d[1] * d[1] - m0.y;
            d[2] = p0.z - gv0.z; d[2] = d[2] * d[2] - m0.z;
            d[3] = p0.w - gv0.w; d[3] = d[3] * d[3] - m0.w;
            d[4] = p1.x - gv1.x; d[4] = d[4] * d[4] - m1.x;
            d[5] = p1.y - gv1.y; d[5] = d[5] * d[5] - m1.y;
            d[6] = p1.z - gv1.z; d[6] = d[6] * d[6] - m1.z;
            d[7] = p1.w - gv1.w; d[7] = d[7] * d[7] - m1.w;
            __half h[8];
            #pragma unroll
            for (int k = 0; k < 8; k++) h[k] = __float2half_rn(d[k]);
            *(uint4*)&g_A16[(size_t)(i * NGALLERY + j) * FEAT + f0] = *(uint4*)h;
        }
    } else {
        const int c = bx - 1024;
        const int f0 = tid * 8;
        float acc = 0.f;
        float w[8];
        if (c < NCLS) {
            float4 w0 = *(const float4*)&W[(size_t)c * FEAT + f0];
            float4 w1 = *(const float4*)&W[(size_t)c * FEAT + f0 + 4];
            w[0] = w0.x; w[1] = w0.y; w[2] = w0.z; w[3] = w0.w;
            w[4] = w1.x; w[5] = w1.y; w[6] = w1.z; w[7] = w1.w;
        } else {
            #pragma unroll
            for (int k = 0; k < 8; k++) w[k] = 0.f;
        }
        __half h[8];
        #pragma unroll
        for (int k = 0; k < 8; k++) {
            float s = g_scale[f0 + k];
            h[k] = __float2half_rn(w[k] * s * WSCALE);
            acc += w[k] * beta[f0 + k];
        }
        *(uint4*)&g_W16[(size_t)c * FEAT + f0] = *(uint4*)h;
        #pragma unroll
        for (int o = 16; o > 0; o >>= 1)
            acc += __shfl_down_sync(0xFFFFFFFFu, acc, o);
        __shared__ float red[8];
        if ((tid & 31) == 0) red[tid >> 5] = acc;
        __syncthreads();
        if (tid == 0) {
            float t = 0.f;
            #pragma unroll
            for (int k = 0; k < 8; k++) t += red[k];
            g_cconst[c] = t + ((c < NCLS) ? bias[c] : 0.f);
        }
    }
}

// ---------------- kernel 3: fp16 HMMA GEMM, 3 CTAs/SM ----------------
// C[16384,768] = A16 * W16^T. CTA tile 128x64x64, 8 warps (4M x 2N, 32x32),
// 3-stage cp.async pipeline, 3 resident CTAs per SM (24 warps).
// Swizzled ldsm addresses are hoisted: for a fixed row, sw128(row*128+x) =
// row*128 + (x ^ ((row&7)<<4)), and rows within a fragment pair differ by 16
// (bit 4 of row), leaving (row&7) unchanged -> per-ik offsets are loop
// constants computed once.
__global__ void __launch_bounds__(THREADS, 3)
gemm_kernel(float* __restrict__ out) {
    extern __shared__ char smem[];
    const uint32_t sb = smem_u32(smem);
    const int tid = threadIdx.x;
    const int lid = tid & 31;
    const int wid = tid >> 5;

    const int ct = blockIdx.x;            // 0..11
    const int rt = blockIdx.y;            // 0..127
    const int n0 = rt * BM;
    const int c0 = ct * BN;

    // producers
    const int pr = tid >> 3;              // row base 0..31
    const int pu = tid & 7;               // 16B chunk in 128B row

    // consumers: warp grid 4 (M) x 2 (N), warp tile 32x32
    const int wm = wid >> 1;              // 0..3
    const int wn = wid & 1;               // 0..1
    const int mbase = wm * 32;
    const int nbase = wn * 32;
    const int a_row  = ((lid >> 3) & 1) * 8 + (lid & 7);
    const int a_colb = (lid >> 4) * 16;
    const int b_row  = (lid >> 4) * 8 + (lid & 7);
    const int b_colb = ((lid >> 3) & 1) * 16;

    // hoisted swizzled offsets (ktile-invariant)
    uint32_t a_off[4], b_off[4];
    {
        const uint32_t ra = (uint32_t)(mbase + a_row);   // fragment 0 row
        const uint32_t rb = (uint32_t)(nbase + b_row);
        const uint32_t ma = (ra & 7u) << 4;
        const uint32_t mb = (rb & 7u) << 4;
        #pragma unroll
        for (int ik = 0; ik < 4; ik++) {
            a_off[ik] = ra * 128u + (((uint32_t)(ik * 32 + a_colb)) ^ ma);
            b_off[ik] = rb * 128u + 16384u + (((uint32_t)(ik * 32 + b_colb)) ^ mb);
        }
    }

    float acc[2][4][4];
    #pragma unroll
    for (int im = 0; im < 2; im++)
        #pragma unroll
        for (int in = 0; in < 4; in++)
            #pragma unroll
            for (int r = 0; r < 4; r++) acc[im][in][r] = 0.f;

    auto issue = [&](int kt) {
        const uint32_t st = (uint32_t)(kt % NSTAGES) * STAGE_BYTES;
        const int k0 = kt * BK;
        // A tile: 128 rows x 128B (4 chunks/thread); .ca -> co-resident CTAs
        // with the same rt share these lines in L1
        #pragma unroll
        for (int c = 0; c < 4; c++) {
            int row = pr + c * 32;
            cp16ca(sb + st + sw128(row * 128 + pu * 16),
                   &g_A16[(size_t)(n0 + row) * FEAT + k0 + pu * 8]);
        }
        // B tile: 64 rows x 128B (2 chunks/thread)
        #pragma unroll
        for (int c = 0; c < 2; c++) {
            int row = pr + c * 32;
            cp16cg(sb + st + 16384 + sw128(row * 128 + pu * 16),
                   &g_W16[(size_t)(c0 + row) * FEAT + k0 + pu * 8]);
        }
    };

    issue(0); CP_COMMIT();
    issue(1); CP_COMMIT();
    issue(2); CP_COMMIT();

    for (int kt = 0; kt < KITERS; kt++) {
        CP_WAIT2();            // stage kt resident (2 newer may pend)
        __syncthreads();

        const uint32_t stb = sb + (uint32_t)(kt % NSTAGES) * STAGE_BYTES;
        #pragma unroll
        for (int ik = 0; ik < 4; ik++) {
            uint32_t a[2][4];
            ldsm4(a[0], stb + a_off[ik]);
            ldsm4(a[1], stb + a_off[ik] + 2048);   // +16 rows, mask invariant
            uint32_t b[8];
            ldsm4(&b[0], stb + b_off[ik]);
            ldsm4(&b[4], stb + b_off[ik] + 2048);
            #pragma unroll
            for (int im = 0; im < 2; im++)
                #pragma unroll
                for (int in = 0; in < 4; in++)
                    mma16816(acc[im][in], a[im], &b[in * 2]);
        }

        __syncthreads();       // reads of stage kt done; buffer reusable
        if (kt + 3 < KITERS) issue(kt + 3);
        CP_COMMIT();           // keep group-count invariant near the tail
    }

    // ---- epilogue: restage through smem, coalesced row stores ----
    float* stage = reinterpret_cast<float*>(smem);   // 128 x EPI_STRIDE fp32
    #pragma unroll
    for (int im = 0; im < 2; im++) {
        #pragma unroll
        for (int in = 0; in < 4; in++) {
            const int r = mbase + im * 16 + (lid >> 2);
            const int c = nbase + in * 8 + (lid & 3) * 2;
            stage[r * EPI_STRIDE + c]           = acc[im][in][0] * WSCALE_INV;
            stage[r * EPI_STRIDE + c + 1]       = acc[im][in][1] * WSCALE_INV;
            stage[(r + 8) * EPI_STRIDE + c]     = acc[im][in][2] * WSCALE_INV;
            stage[(r + 8) * EPI_STRIDE + c + 1] = acc[im][in][3] * WSCALE_INV;
        }
    }
    __syncthreads();
    const int col = c0 + (tid & 63);
    const int rbase = (tid >> 6) * 32;          // 0,32,64,96
    if (col < NCLS) {
        const float cc = g_cconst[col];
        #pragma unroll 8
        for (int r = 0; r < 32; r++)
            out[(size_t)(n0 + rbase + r) * NCLS + col] =
                stage[(rbase + r) * EPI_STRIDE + (tid & 63)] + cc;
    }
}

// ---------------- launch ----------------
extern "C" void kernel_launch(void* const* d_in, const int* in_sizes, int n_in,
                              void* d_out, int out_size) {
    const float* probe   = (const float*)d_in[0];
    const float* gallery = (const float*)d_in[1];
    const float* gamma   = (const float*)d_in[2];
    const float* beta    = (const float*)d_in[3];
    const float* W       = (const float*)d_in[4];
    const float* bias    = (const float*)d_in[5];
    float* out = (float*)d_out;

    stats_kernel<<<8, 256>>>(probe, gallery, gamma);
    fused_prep_kernel<<<1792, 256>>>(probe, gallery, W, beta, bias);

    static bool attr_set = false;
    if (!attr_set) {
        cudaFuncSetAttribute(gemm_kernel,
                             cudaFuncAttributeMaxDynamicSharedMemorySize, SMEM_TOTAL);
        attr_set = true;
    }
    gemm_kernel<<<dim3(12, 128, 1), THREADS, SMEM_TOTAL>>>(out);
}

// round 11
// speedup vs baseline: 1.3166x; 1.3166x over previous
#include <cuda_runtime.h>
#include <cuda_fp16.h>
#include <cstdint>

#define FEAT      2048
#define NPROBE    64
#define NGALLERY  256
#define NROWS     16384           // NPROBE * NGALLERY
#define NCLS      751
#define NPAD      768
#define BN_EPS    1e-5f

#define BM        128
#define BN        64
#define BK        64
#define KITERS    (FEAT / BK)     // 32
#define THREADS   256             // 8 warps (4M x 2N), warp tile 32x32
#define WSCALE    64.0f
#define WSCALE_INV (1.0f / 64.0f)

// 3-stage smem pipeline: per stage A 16KB + B 8KB = 24KB -> 72KB, 3 CTAs/SM
#define STAGE_BYTES 24576
#define NSTAGES     3
#define SMEM_TOTAL  (NSTAGES * STAGE_BYTES)   // 73728 B

#define EPI_STRIDE  68            // fp32 words

#define NPART 10

// ---------------- device scratch ----------------
__device__ __align__(16) float g_part[NPART * 4 * FEAT];
__device__ __align__(16) float g_scale[FEAT];
__device__ __align__(16) float g_mean[FEAT];
__device__ __align__(16) float g_cconst[NPAD];
__device__ __align__(16) __half g_W16[NPAD * FEAT];          // 3 MB
__device__ __align__(16) __half g_A16[(size_t)NROWS * FEAT]; // 64 MB

// ---------------- helpers ----------------
__device__ __forceinline__ uint32_t smem_u32(const void* p) {
    uint32_t a;
    asm("{ .reg .u64 t; cvta.to.shared.u64 t, %1; cvt.u32.u64 %0, t; }"
        : "=r"(a) : "l"(p));
    return a;
}
__device__ __forceinline__ uint32_t sw128(uint32_t off) {
    return off ^ ((off >> 3) & 0x70);
}
__device__ __forceinline__ void cp16(uint32_t dst, const void* src) {
    asm volatile("cp.async.cg.shared.global [%0], [%1], 16;"
                 :: "r"(dst), "l"(src) : "memory");
}
#define CP_COMMIT() asm volatile("cp.async.commit_group;" ::: "memory")
#define CP_WAIT2()  asm volatile("cp.async.wait_group 2;" ::: "memory")

__device__ __forceinline__ void ldsm4(uint32_t* r, uint32_t addr) {
    asm volatile("ldmatrix.sync.aligned.m8n8.x4.shared.b16 {%0,%1,%2,%3}, [%4];"
                 : "=r"(r[0]), "=r"(r[1]), "=r"(r[2]), "=r"(r[3]) : "r"(addr));
}
__device__ __forceinline__ void mma16816(float* c, const uint32_t* a,
                                         const uint32_t* b) {
    asm volatile(
        "mma.sync.aligned.m16n8k16.row.col.f32.f16.f16.f32 "
        "{%0,%1,%2,%3}, {%4,%5,%6,%7}, {%8,%9}, {%0,%1,%2,%3};"
        : "+f"(c[0]), "+f"(c[1]), "+f"(c[2]), "+f"(c[3])
        : "r"(a[0]), "r"(a[1]), "r"(a[2]), "r"(a[3]), "r"(b[0]), "r"(b[1]));
}

// ---------------- kernel 1a: partial moments (80 blocks) ----------------
__global__ void stats_part_kernel(const float* __restrict__ probe,
                                  const float* __restrict__ gallery) {
    const int f = blockIdx.x * 256 + threadIdx.x;
    const int y = blockIdx.y;
    const float* src = (y < 2) ? probe : gallery;
    const int r0 = (y < 2) ? y * 32 : (y - 2) * 32;
    float s1 = 0.f, s2 = 0.f, s3 = 0.f, s4 = 0.f;
    #pragma unroll 8
    for (int r = 0; r < 32; r++) {
        float v = src[(size_t)(r0 + r) * FEAT + f];
        float v2 = v * v;
        s1 += v; s2 += v2; s3 += v2 * v; s4 += v2 * v2;
    }
    g_part[(y * 4 + 0) * FEAT + f] = s1;
    g_part[(y * 4 + 1) * FEAT + f] = s2;
    g_part[(y * 4 + 2) * FEAT + f] = s3;
    g_part[(y * 4 + 3) * FEAT + f] = s4;
}

// ---------------- kernel 1b: finalize BN stats ----------------
__global__ void stats_final_kernel(const float* __restrict__ gamma) {
    const int f = blockIdx.x * 256 + threadIdx.x;
    float sp1 = 0.f, sp2 = 0.f, sp3 = 0.f, sp4 = 0.f;
    float sg1 = 0.f, sg2 = 0.f, sg3 = 0.f, sg4 = 0.f;
    #pragma unroll
    for (int y = 0; y < 2; y++) {
        sp1 += g_part[(y * 4 + 0) * FEAT + f];
        sp2 += g_part[(y * 4 + 1) * FEAT + f];
        sp3 += g_part[(y * 4 + 2) * FEAT + f];
        sp4 += g_part[(y * 4 + 3) * FEAT + f];
    }
    #pragma unroll
    for (int y = 2; y < 10; y++) {
        sg1 += g_part[(y * 4 + 0) * FEAT + f];
        sg2 += g_part[(y * 4 + 1) * FEAT + f];
        sg3 += g_part[(y * 4 + 2) * FEAT + f];
        sg4 += g_part[(y * 4 + 3) * FEAT + f];
    }
    const float ip = 1.f / NPROBE, ig = 1.f / NGALLERY;
    float mp1 = sp1 * ip, mp2 = sp2 * ip, mp3 = sp3 * ip, mp4 = sp4 * ip;
    float mg1 = sg1 * ig, mg2 = sg2 * ig, mg3 = sg3 * ig, mg4 = sg4 * ig;
    // exact identities: the BN batch is the full (i,j) cartesian product
    float mean = mp2 + mg2 - 2.f * mp1 * mg1;
    float ed2  = mp4 - 4.f * mp3 * mg1 + 6.f * mp2 * mg2 - 4.f * mp1 * mg3 + mg4;
    float var  = ed2 - mean * mean;
    g_mean[f]  = mean;
    g_scale[f] = gamma[f] * rsqrtf(var + BN_EPS);
}

// ---------------- kernel 2: fused A16 build + W prep ----------------
// blocks [0,4096): A16 for (i, 4-row gallery chunk)
// blocks [4096,4864): W16 row + cconst
__global__ void fused_prep_kernel(const float* __restrict__ probe,
                                  const float* __restrict__ gallery,
                                  const float* __restrict__ W,
                                  const float* __restrict__ beta,
                                  const float* __restrict__ bias) {
    const int bx = blockIdx.x;
    const int tid = threadIdx.x;
    if (bx < 4096) {
        const int i = bx >> 6;            // probe row 0..63
        const int jc = bx & 63;           // 4-row chunk 0..63
        const int f0 = tid * 8;
        float4 p0 = *(const float4*)&probe[(size_t)i * FEAT + f0];
        float4 p1 = *(const float4*)&probe[(size_t)i * FEAT + f0 + 4];
        float4 m0 = *(const float4*)&g_mean[f0];
        float4 m1 = *(const float4*)&g_mean[f0 + 4];
        #pragma unroll
        for (int jj = 0; jj < 4; jj++) {
            const int j = jc * 4 + jj;
            float4 gv0 = *(const float4*)&gallery[(size_t)j * FEAT + f0];
            float4 gv1 = *(const float4*)&gallery[(size_t)j * FEAT + f0 + 4];
            float d[8];
            d[0] = p0.x - gv0.x; d[0] = d[0] * d[0] - m0.x;
            d[1] = p0.y - gv0.y; d[1] = d[1] * d[1] - m0.y;
            d[2] = p0.z - gv0.z; d[2] = d[2] * d[2] - m0.z;
            d[3] = p0.w - gv0.w; d[3] = d[3] * d[3] - m0.w;
            d[4] = p1.x - gv1.x; d[4] = d[4] * d[4] - m1.x;
            d[5] = p1.y - gv1.y; d[5] = d[5] * d[5] - m1.y;
            d[6] = p1.z - gv1.z; d[6] = d[6] * d[6] - m1.z;
            d[7] = p1.w - gv1.w; d[7] = d[7] * d[7] - m1.w;
            __half h[8];
            #pragma unroll
            for (int k = 0; k < 8; k++) h[k] = __float2half_rn(d[k]);
            *(uint4*)&g_A16[(size_t)(i * NGALLERY + j) * FEAT + f0] = *(uint4*)h;
        }
    } else {
        const int c = bx - 4096;
        const int f0 = tid * 8;
        float acc = 0.f;
        float w[8];
        if (c < NCLS) {
            float4 w0 = *(const float4*)&W[(size_t)c * FEAT + f0];
            float4 w1 = *(const float4*)&W[(size_t)c * FEAT + f0 + 4];
            w[0] = w0.x; w[1] = w0.y; w[2] = w0.z; w[3] = w0.w;
            w[4] = w1.x; w[5] = w1.y; w[6] = w1.z; w[7] = w1.w;
        } else {
            #pragma unroll
            for (int k = 0; k < 8; k++) w[k] = 0.f;
        }
        __half h[8];
        #pragma unroll
        for (int k = 0; k < 8; k++) {
            float s = g_scale[f0 + k];
            h[k] = __float2half_rn(w[k] * s * WSCALE);
            acc += w[k] * beta[f0 + k];
        }
        *(uint4*)&g_W16[(size_t)c * FEAT + f0] = *(uint4*)h;
        #pragma unroll
        for (int o = 16; o > 0; o >>= 1)
            acc += __shfl_down_sync(0xFFFFFFFFu, acc, o);
        __shared__ float red[8];
        if ((tid & 31) == 0) red[tid >> 5] = acc;
        __syncthreads();
        if (tid == 0) {
            float t = 0.f;
            #pragma unroll
            for (int k = 0; k < 8; k++) t += red[k];
            g_cconst[c] = t + ((c < NCLS) ? bias[c] : 0.f);
        }
    }
}

// ---------------- kernel 3: fp16 HMMA GEMM, 3 CTAs/SM (R9 config) --------
// C[16384,768] = A16 * W16^T. CTA tile 128x64x64, 8 warps (4M x 2N, 32x32),
// 3-stage cp.async pipeline (.cg only), 3 resident CTAs per SM.
__global__ void __launch_bounds__(THREADS, 3)
gemm_kernel(float* __restrict__ out) {
    extern __shared__ char smem[];
    const uint32_t sb = smem_u32(smem);
    const int tid = threadIdx.x;
    const int lid = tid & 31;
    const int wid = tid >> 5;

    const int ct = blockIdx.x;            // 0..11
    const int rt = blockIdx.y;            // 0..127
    const int n0 = rt * BM;
    const int c0 = ct * BN;

    const int pr = tid >> 3;              // row base 0..31
    const int pu = tid & 7;               // 16B chunk in 128B row

    const int wm = wid >> 1;              // 0..3
    const int wn = wid & 1;               // 0..1
    const int mbase = wm * 32;
    const int nbase = wn * 32;
    const int a_row  = ((lid >> 3) & 1) * 8 + (lid & 7);
    const int a_colb = (lid >> 4) * 16;
    const int b_row  = (lid >> 4) * 8 + (lid & 7);
    const int b_colb = ((lid >> 3) & 1) * 16;

    float acc[2][4][4];
    #pragma unroll
    for (int im = 0; im < 2; im++)
        #pragma unroll
        for (int in = 0; in < 4; in++)
            #pragma unroll
            for (int r = 0; r < 4; r++) acc[im][in][r] = 0.f;

    auto issue = [&](int kt) {
        const uint32_t st = (uint32_t)(kt % NSTAGES) * STAGE_BYTES;
        const int k0 = kt * BK;
        #pragma unroll
        for (int c = 0; c < 4; c++) {
            int row = pr + c * 32;
            cp16(sb + st + sw128(row * 128 + pu * 16),
                 &g_A16[(size_t)(n0 + row) * FEAT + k0 + pu * 8]);
        }
        #pragma unroll
        for (int c = 0; c < 2; c++) {
            int row = pr + c * 32;
            cp16(sb + st + 16384 + sw128(row * 128 + pu * 16),
                 &g_W16[(size_t)(c0 + row) * FEAT + k0 + pu * 8]);
        }
    };

    issue(0); CP_COMMIT();
    issue(1); CP_COMMIT();
    issue(2); CP_COMMIT();

    for (int kt = 0; kt < KITERS; kt++) {
        CP_WAIT2();            // stage kt resident (2 newer may pend)
        __syncthreads();

        const uint32_t abuf = sb + (uint32_t)(kt % NSTAGES) * STAGE_BYTES;
        const uint32_t bbuf = abuf + 16384;
        #pragma unroll
        for (int ik = 0; ik < 4; ik++) {
            uint32_t a[2][4];
            #pragma unroll
            for (int im = 0; im < 2; im++)
                ldsm4(a[im], abuf +
                      sw128((mbase + im * 16 + a_row) * 128 + ik * 32 + a_colb));
            uint32_t b[8];
            #pragma unroll
            for (int nb = 0; nb < 2; nb++)
                ldsm4(&b[nb * 4], bbuf +
                      sw128((nbase + nb * 16 + b_row) * 128 + ik * 32 + b_colb));
            #pragma unroll
            for (int im = 0; im < 2; im++)
                #pragma unroll
                for (int in = 0; in < 4; in++)
                    mma16816(acc[im][in], a[im], &b[in * 2]);
        }

        __syncthreads();       // reads of stage kt done; buffer reusable
        if (kt + 3 < KITERS) issue(kt + 3);
        CP_COMMIT();           // keep group-count invariant near the tail
    }

    // ---- epilogue: restage through smem, coalesced row stores ----
    float* stage = reinterpret_cast<float*>(smem);   // 128 x EPI_STRIDE fp32
    #pragma unroll
    for (int im = 0; im < 2; im++) {
        #pragma unroll
        for (int in = 0; in < 4; in++) {
            const int r = mbase + im * 16 + (lid >> 2);
            const int c = nbase + in * 8 + (lid & 3) * 2;
            stage[r * EPI_STRIDE + c]           = acc[im][in][0] * WSCALE_INV;
            stage[r * EPI_STRIDE + c + 1]       = acc[im][in][1] * WSCALE_INV;
            stage[(r + 8) * EPI_STRIDE + c]     = acc[im][in][2] * WSCALE_INV;
            stage[(r + 8) * EPI_STRIDE + c + 1] = acc[im][in][3] * WSCALE_INV;
        }
    }
    __syncthreads();
    const int col = c0 + (tid & 63);
    const int rbase = (tid >> 6) * 32;          // 0,32,64,96
    if (col < NCLS) {
        const float cc = g_cconst[col];
        #pragma unroll 8
        for (int r = 0; r < 32; r++)
            out[(size_t)(n0 + rbase + r) * NCLS + col] =
                stage[(rbase + r) * EPI_STRIDE + (tid & 63)] + cc;
    }
}

// ---------------- launch ----------------
extern "C" void kernel_launch(void* const* d_in, const int* in_sizes, int n_in,
                              void* d_out, int out_size) {
    const float* probe   = (const float*)d_in[0];
    const float* gallery = (const float*)d_in[1];
    const float* gamma   = (const float*)d_in[2];
    const float* beta    = (const float*)d_in[3];
    const float* W       = (const float*)d_in[4];
    const float* bias    = (const float*)d_in[5];
    float* out = (float*)d_out;

    stats_part_kernel<<<dim3(8, 10), 256>>>(probe, gallery);
    stats_final_kernel<<<8, 256>>>(gamma);
    fused_prep_kernel<<<4864, 256>>>(probe, gallery, W, beta, bias);

    static bool attr_set = false;
    if (!attr_set) {
        cudaFuncSetAttribute(gemm_kernel,
                             cudaFuncAttributeMaxDynamicSharedMemorySize, SMEM_TOTAL);
        attr_set = true;
    }
    gemm_kernel<<<dim3(12, 128, 1), THREADS, SMEM_TOTAL>>>(out);
}

// round 12
// speedup vs baseline: 1.3230x; 1.0048x over previous
#include <cuda_runtime.h>
#include <cuda_fp16.h>
#include <cstdint>

#define FEAT      2048
#define NPROBE    64
#define NGALLERY  256
#define NROWS     16384           // NPROBE * NGALLERY
#define NCLS      751
#define NPAD      768
#define BN_EPS    1e-5f

#define BM        128
#define BN        64
#define BK        64
#define KITERS    (FEAT / BK)     // 32
#define THREADS   256             // 8 warps (4M x 2N), warp tile 32x32
#define WSCALE    64.0f
#define WSCALE_INV (1.0f / 64.0f)

// 3-stage smem pipeline: per stage A 16KB + B 8KB = 24KB -> 72KB, 3 CTAs/SM
#define STAGE_BYTES 24576
#define NSTAGES     3
#define SMEM_TOTAL  (NSTAGES * STAGE_BYTES)   // 73728 B

#define EPI_STRIDE  68            // fp32 words

#define NPART 10

// ---------------- device scratch ----------------
__device__ __align__(16) float g_part[NPART * 4 * FEAT];
__device__ __align__(16) float g_scale[FEAT];
__device__ __align__(16) float g_mean[FEAT];
__device__ __align__(16) float g_cconst[NPAD];
__device__ __align__(16) __half g_W16[NPAD * FEAT];          // 3 MB
__device__ __align__(16) __half g_A16[(size_t)NROWS * FEAT]; // 64 MB

// ---------------- helpers ----------------
__device__ __forceinline__ uint32_t smem_u32(const void* p) {
    uint32_t a;
    asm("{ .reg .u64 t; cvta.to.shared.u64 t, %1; cvt.u32.u64 %0, t; }"
        : "=r"(a) : "l"(p));
    return a;
}
__device__ __forceinline__ uint32_t sw128(uint32_t off) {
    return off ^ ((off >> 3) & 0x70);
}
__device__ __forceinline__ void cp16(uint32_t dst, const void* src) {
    asm volatile("cp.async.cg.shared.global [%0], [%1], 16;"
                 :: "r"(dst), "l"(src) : "memory");
}
#define CP_COMMIT() asm volatile("cp.async.commit_group;" ::: "memory")
#define CP_WAIT2()  asm volatile("cp.async.wait_group 2;" ::: "memory")

__device__ __forceinline__ void ldsm4(uint32_t* r, uint32_t addr) {
    asm volatile("ldmatrix.sync.aligned.m8n8.x4.shared.b16 {%0,%1,%2,%3}, [%4];"
                 : "=r"(r[0]), "=r"(r[1]), "=r"(r[2]), "=r"(r[3]) : "r"(addr));
}
__device__ __forceinline__ void mma16816(float* c, const uint32_t* a,
                                         const uint32_t* b) {
    asm volatile(
        "mma.sync.aligned.m16n8k16.row.col.f32.f16.f16.f32 "
        "{%0,%1,%2,%3}, {%4,%5,%6,%7}, {%8,%9}, {%0,%1,%2,%3};"
        : "+f"(c[0]), "+f"(c[1]), "+f"(c[2]), "+f"(c[3])
        : "r"(a[0]), "r"(a[1]), "r"(a[2]), "r"(a[3]), "r"(b[0]), "r"(b[1]));
}

// ---------------- kernel 1a: partial moments (80 blocks) ----------------
__global__ void stats_part_kernel(const float* __restrict__ probe,
                                  const float* __restrict__ gallery) {
    const int f = blockIdx.x * 256 + threadIdx.x;
    const int y = blockIdx.y;
    const float* src = (y < 2) ? probe : gallery;
    const int r0 = (y < 2) ? y * 32 : (y - 2) * 32;
    float s1 = 0.f, s2 = 0.f, s3 = 0.f, s4 = 0.f;
    #pragma unroll 8
    for (int r = 0; r < 32; r++) {
        float v = src[(size_t)(r0 + r) * FEAT + f];
        float v2 = v * v;
        s1 += v; s2 += v2; s3 += v2 * v; s4 += v2 * v2;
    }
    g_part[(y * 4 + 0) * FEAT + f] = s1;
    g_part[(y * 4 + 1) * FEAT + f] = s2;
    g_part[(y * 4 + 2) * FEAT + f] = s3;
    g_part[(y * 4 + 3) * FEAT + f] = s4;
}

// ---------------- kernel 1b: finalize BN stats ----------------
__global__ void stats_final_kernel(const float* __restrict__ gamma) {
    const int f = blockIdx.x * 256 + threadIdx.x;
    float sp1 = 0.f, sp2 = 0.f, sp3 = 0.f, sp4 = 0.f;
    float sg1 = 0.f, sg2 = 0.f, sg3 = 0.f, sg4 = 0.f;
    #pragma unroll
    for (int y = 0; y < 2; y++) {
        sp1 += g_part[(y * 4 + 0) * FEAT + f];
        sp2 += g_part[(y * 4 + 1) * FEAT + f];
        sp3 += g_part[(y * 4 + 2) * FEAT + f];
        sp4 += g_part[(y * 4 + 3) * FEAT + f];
    }
    #pragma unroll
    for (int y = 2; y < 10; y++) {
        sg1 += g_part[(y * 4 + 0) * FEAT + f];
        sg2 += g_part[(y * 4 + 1) * FEAT + f];
        sg3 += g_part[(y * 4 + 2) * FEAT + f];
        sg4 += g_part[(y * 4 + 3) * FEAT + f];
    }
    const float ip = 1.f / NPROBE, ig = 1.f / NGALLERY;
    float mp1 = sp1 * ip, mp2 = sp2 * ip, mp3 = sp3 * ip, mp4 = sp4 * ip;
    float mg1 = sg1 * ig, mg2 = sg2 * ig, mg3 = sg3 * ig, mg4 = sg4 * ig;
    // exact identities: the BN batch is the full (i,j) cartesian product
    float mean = mp2 + mg2 - 2.f * mp1 * mg1;
    float ed2  = mp4 - 4.f * mp3 * mg1 + 6.f * mp2 * mg2 - 4.f * mp1 * mg3 + mg4;
    float var  = ed2 - mean * mean;
    g_mean[f]  = mean;
    g_scale[f] = gamma[f] * rsqrtf(var + BN_EPS);
}

// ---------------- kernel 2: fused A16 build (tiled) + W prep ----------------
// blocks [0,128): cartesian tile 8 probes x 16 gallery rows -> 128 A16 rows.
//   reads 24 MB total (vs 130 MB untiled), writes 64 MB coalesced.
// blocks [128,896): W16 row + cconst.
__global__ void fused_prep_kernel(const float* __restrict__ probe,
                                  const float* __restrict__ gallery,
                                  const float* __restrict__ W,
                                  const float* __restrict__ beta,
                                  const float* __restrict__ bias) {
    const int bx = blockIdx.x;
    const int tid = threadIdx.x;
    const int f0 = tid * 8;
    if (bx < 128) {
        const int pc = bx >> 4;           // probe chunk 0..7 (8 rows)
        const int jc = bx & 15;           // gallery chunk 0..15 (16 rows)
        // probe chunk + mean in registers
        float p[8][8];
        #pragma unroll
        for (int ii = 0; ii < 8; ii++) {
            float4 a = *(const float4*)&probe[(size_t)(pc * 8 + ii) * FEAT + f0];
            float4 b = *(const float4*)&probe[(size_t)(pc * 8 + ii) * FEAT + f0 + 4];
            p[ii][0] = a.x; p[ii][1] = a.y; p[ii][2] = a.z; p[ii][3] = a.w;
            p[ii][4] = b.x; p[ii][5] = b.y; p[ii][6] = b.z; p[ii][7] = b.w;
        }
        float m[8];
        {
            float4 m0 = *(const float4*)&g_mean[f0];
            float4 m1 = *(const float4*)&g_mean[f0 + 4];
            m[0] = m0.x; m[1] = m0.y; m[2] = m0.z; m[3] = m0.w;
            m[4] = m1.x; m[5] = m1.y; m[6] = m1.z; m[7] = m1.w;
        }
        #pragma unroll 2
        for (int jj = 0; jj < 16; jj++) {
            const int j = jc * 16 + jj;
            float g[8];
            {
                float4 g0 = *(const float4*)&gallery[(size_t)j * FEAT + f0];
                float4 g1 = *(const float4*)&gallery[(size_t)j * FEAT + f0 + 4];
                g[0] = g0.x; g[1] = g0.y; g[2] = g0.z; g[3] = g0.w;
                g[4] = g1.x; g[5] = g1.y; g[6] = g1.z; g[7] = g1.w;
            }
            #pragma unroll
            for (int ii = 0; ii < 8; ii++) {
                __half h[8];
                #pragma unroll
                for (int k = 0; k < 8; k++) {
                    float d = p[ii][k] - g[k];
                    h[k] = __float2half_rn(d * d - m[k]);
                }
                const int row = (pc * 8 + ii) * NGALLERY + j;
                *(uint4*)&g_A16[(size_t)row * FEAT + f0] = *(uint4*)h;
            }
        }
    } else {
        const int c = bx - 128;
        float acc = 0.f;
        float w[8];
        if (c < NCLS) {
            float4 w0 = *(const float4*)&W[(size_t)c * FEAT + f0];
            float4 w1 = *(const float4*)&W[(size_t)c * FEAT + f0 + 4];
            w[0] = w0.x; w[1] = w0.y; w[2] = w0.z; w[3] = w0.w;
            w[4] = w1.x; w[5] = w1.y; w[6] = w1.z; w[7] = w1.w;
        } else {
            #pragma unroll
            for (int k = 0; k < 8; k++) w[k] = 0.f;
        }
        __half h[8];
        #pragma unroll
        for (int k = 0; k < 8; k++) {
            float s = g_scale[f0 + k];
            h[k] = __float2half_rn(w[k] * s * WSCALE);
            acc += w[k] * beta[f0 + k];
        }
        *(uint4*)&g_W16[(size_t)c * FEAT + f0] = *(uint4*)h;
        #pragma unroll
        for (int o = 16; o > 0; o >>= 1)
            acc += __shfl_down_sync(0xFFFFFFFFu, acc, o);
        __shared__ float red[8];
        if ((tid & 31) == 0) red[tid >> 5] = acc;
        __syncthreads();
        if (tid == 0) {
            float t = 0.f;
            #pragma unroll
            for (int k = 0; k < 8; k++) t += red[k];
            g_cconst[c] = t + ((c < NCLS) ? bias[c] : 0.f);
        }
    }
}

// ---------------- kernel 3: fp16 HMMA GEMM, 3 CTAs/SM (frozen R9 config) --
// C[16384,768] = A16 * W16^T. CTA tile 128x64x64, 8 warps (4M x 2N, 32x32),
// 3-stage cp.async pipeline (.cg only), 3 resident CTAs per SM.
__global__ void __launch_bounds__(THREADS, 3)
gemm_kernel(float* __restrict__ out) {
    extern __shared__ char smem[];
    const uint32_t sb = smem_u32(smem);
    const int tid = threadIdx.x;
    const int lid = tid & 31;
    const int wid = tid >> 5;

    const int ct = blockIdx.x;            // 0..11
    const int rt = blockIdx.y;            // 0..127
    const int n0 = rt * BM;
    const int c0 = ct * BN;

    const int pr = tid >> 3;              // row base 0..31
    const int pu = tid & 7;               // 16B chunk in 128B row

    const int wm = wid >> 1;              // 0..3
    const int wn = wid & 1;               // 0..1
    const int mbase = wm * 32;
    const int nbase = wn * 32;
    const int a_row  = ((lid >> 3) & 1) * 8 + (lid & 7);
    const int a_colb = (lid >> 4) * 16;
    const int b_row  = (lid >> 4) * 8 + (lid & 7);
    const int b_colb = ((lid >> 3) & 1) * 16;

    float acc[2][4][4];
    #pragma unroll
    for (int im = 0; im < 2; im++)
        #pragma unroll
        for (int in = 0; in < 4; in++)
            #pragma unroll
            for (int r = 0; r < 4; r++) acc[im][in][r] = 0.f;

    auto issue = [&](int kt) {
        const uint32_t st = (uint32_t)(kt % NSTAGES) * STAGE_BYTES;
        const int k0 = kt * BK;
        #pragma unroll
        for (int c = 0; c < 4; c++) {
            int row = pr + c * 32;
            cp16(sb + st + sw128(row * 128 + pu * 16),
                 &g_A16[(size_t)(n0 + row) * FEAT + k0 + pu * 8]);
        }
        #pragma unroll
        for (int c = 0; c < 2; c++) {
            int row = pr + c * 32;
            cp16(sb + st + 16384 + sw128(row * 128 + pu * 16),
                 &g_W16[(size_t)(c0 + row) * FEAT + k0 + pu * 8]);
        }
    };

    issue(0); CP_COMMIT();
    issue(1); CP_COMMIT();
    issue(2); CP_COMMIT();

    for (int kt = 0; kt < KITERS; kt++) {
        CP_WAIT2();            // stage kt resident (2 newer may pend)
        __syncthreads();

        const uint32_t abuf = sb + (uint32_t)(kt % NSTAGES) * STAGE_BYTES;
        const uint32_t bbuf = abuf + 16384;
        #pragma unroll
        for (int ik = 0; ik < 4; ik++) {
            uint32_t a[2][4];
            #pragma unroll
            for (int im = 0; im < 2; im++)
                ldsm4(a[im], abuf +
                      sw128((mbase + im * 16 + a_row) * 128 + ik * 32 + a_colb));
            uint32_t b[8];
            #pragma unroll
            for (int nb = 0; nb < 2; nb++)
                ldsm4(&b[nb * 4], bbuf +
                      sw128((nbase + nb * 16 + b_row) * 128 + ik * 32 + b_colb));
            #pragma unroll
            for (int im = 0; im < 2; im++)
                #pragma unroll
                for (int in = 0; in < 4; in++)
                    mma16816(acc[im][in], a[im], &b[in * 2]);
        }

        __syncthreads();       // reads of stage kt done; buffer reusable
        if (kt + 3 < KITERS) issue(kt + 3);
        CP_COMMIT();           // keep group-count invariant near the tail
    }

    // ---- epilogue: restage through smem, coalesced row stores ----
    float* stage = reinterpret_cast<float*>(smem);   // 128 x EPI_STRIDE fp32
    #pragma unroll
    for (int im = 0; im < 2; im++) {
        #pragma unroll
        for (int in = 0; in < 4; in++) {
            const int r = mbase + im * 16 + (lid >> 2);
            const int c = nbase + in * 8 + (lid & 3) * 2;
            stage[r * EPI_STRIDE + c]           = acc[im][in][0] * WSCALE_INV;
            stage[r * EPI_STRIDE + c + 1]       = acc[im][in][1] * WSCALE_INV;
            stage[(r + 8) * EPI_STRIDE + c]     = acc[im][in][2] * WSCALE_INV;
            stage[(r + 8) * EPI_STRIDE + c + 1] = acc[im][in][3] * WSCALE_INV;
        }
    }
    __syncthreads();
    const int col = c0 + (tid & 63);
    const int rbase = (tid >> 6) * 32;          // 0,32,64,96
    if (col < NCLS) {
        const float cc = g_cconst[col];
        #pragma unroll 8
        for (int r = 0; r < 32; r++)
            out[(size_t)(n0 + rbase + r) * NCLS + col] =
                stage[(rbase + r) * EPI_STRIDE + (tid & 63)] + cc;
    }
}

// ---------------- launch ----------------
extern "C" void kernel_launch(void* const* d_in, const int* in_sizes, int n_in,
                              void* d_out, int out_size) {
    const float* probe   = (const float*)d_in[0];
    const float* gallery = (const float*)d_in[1];
    const float* gamma   = (const float*)d_in[2];
    const float* beta    = (const float*)d_in[3];
    const float* W       = (const float*)d_in[4];
    const float* bias    = (const float*)d_in[5];
    float* out = (float*)d_out;

    stats_part_kernel<<<dim3(8, 10), 256>>>(probe, gallery);
    stats_final_kernel<<<8, 256>>>(gamma);
    fused_prep_kernel<<<896, 256>>>(probe, gallery, W, beta, bias);

    static bool attr_set = false;
    if (!attr_set) {
        cudaFuncSetAttribute(gemm_kernel,
                             cudaFuncAttributeMaxDynamicSharedMemorySize, SMEM_TOTAL);
        attr_set = true;
    }
    gemm_kernel<<<dim3(12, 128, 1), THREADS, SMEM_TOTAL>>>(out);
}

// round 13
// speedup vs baseline: 1.3717x; 1.0369x over previous
#include <cuda_runtime.h>
#include <cuda_fp16.h>
#include <cstdint>

#define FEAT      2048
#define NPROBE    64
#define NGALLERY  256
#define NROWS     16384           // NPROBE * NGALLERY
#define NCLS      751
#define NPAD      768
#define BN_EPS    1e-5f

#define BM        128
#define BN        64
#define BK        64
#define KITERS    (FEAT / BK)     // 32
#define THREADS   256             // 8 warps (4M x 2N), warp tile 32x32
#define WSCALE    64.0f
#define WSCALE_INV (1.0f / 64.0f)

// 3-stage smem pipeline: per stage A 16KB + B 8KB = 24KB -> 72KB, 3 CTAs/SM
#define STAGE_BYTES 24576
#define NSTAGES     3
#define SMEM_TOTAL  (NSTAGES * STAGE_BYTES)   // 73728 B

#define EPI_STRIDE  68            // fp32 words

#define NPART 10

// ---------------- device scratch ----------------
__device__ __align__(16) float g_part[NPART * 4 * FEAT];
__device__ __align__(16) float g_scale[FEAT];
__device__ __align__(16) float g_mean[FEAT];
__device__ __align__(16) float g_cconst[NPAD];
__device__ __align__(16) __half g_W16[NPAD * FEAT];          // 3 MB
__device__ __align__(16) __half g_A16[(size_t)NROWS * FEAT]; // 64 MB

// ---------------- helpers ----------------
__device__ __forceinline__ uint32_t smem_u32(const void* p) {
    uint32_t a;
    asm("{ .reg .u64 t; cvta.to.shared.u64 t, %1; cvt.u32.u64 %0, t; }"
        : "=r"(a) : "l"(p));
    return a;
}
__device__ __forceinline__ uint32_t sw128(uint32_t off) {
    return off ^ ((off >> 3) & 0x70);
}
__device__ __forceinline__ void cp16(uint32_t dst, const void* src) {
    asm volatile("cp.async.cg.shared.global [%0], [%1], 16;"
                 :: "r"(dst), "l"(src) : "memory");
}
#define CP_COMMIT() asm volatile("cp.async.commit_group;" ::: "memory")
#define CP_WAIT2()  asm volatile("cp.async.wait_group 2;" ::: "memory")

__device__ __forceinline__ void ldsm4(uint32_t* r, uint32_t addr) {
    asm volatile("ldmatrix.sync.aligned.m8n8.x4.shared.b16 {%0,%1,%2,%3}, [%4];"
                 : "=r"(r[0]), "=r"(r[1]), "=r"(r[2]), "=r"(r[3]) : "r"(addr));
}
__device__ __forceinline__ void mma16816(float* c, const uint32_t* a,
                                         const uint32_t* b) {
    asm volatile(
        "mma.sync.aligned.m16n8k16.row.col.f32.f16.f16.f32 "
        "{%0,%1,%2,%3}, {%4,%5,%6,%7}, {%8,%9}, {%0,%1,%2,%3};"
        : "+f"(c[0]), "+f"(c[1]), "+f"(c[2]), "+f"(c[3])
        : "r"(a[0]), "r"(a[1]), "r"(a[2]), "r"(a[3]), "r"(b[0]), "r"(b[1]));
}

// ---------------- kernel A: A16[i*256+j][f] = fp16((p-g)^2), NO deps ------
// Cartesian tile 8 probes x 16 gallery rows per block; 128 blocks.
// Mean is folded into cconst instead (BN centering is linear).
__global__ void a16_kernel(const float* __restrict__ probe,
                           const float* __restrict__ gallery) {
    const int bx = blockIdx.x;
    const int tid = threadIdx.x;
    const int f0 = tid * 8;
    const int pc = bx >> 4;           // probe chunk 0..7 (8 rows)
    const int jc = bx & 15;           // gallery chunk 0..15 (16 rows)
    float p[8][8];
    #pragma unroll
    for (int ii = 0; ii < 8; ii++) {
        float4 a = *(const float4*)&probe[(size_t)(pc * 8 + ii) * FEAT + f0];
        float4 b = *(const float4*)&probe[(size_t)(pc * 8 + ii) * FEAT + f0 + 4];
        p[ii][0] = a.x; p[ii][1] = a.y; p[ii][2] = a.z; p[ii][3] = a.w;
        p[ii][4] = b.x; p[ii][5] = b.y; p[ii][6] = b.z; p[ii][7] = b.w;
    }
    #pragma unroll 2
    for (int jj = 0; jj < 16; jj++) {
        const int j = jc * 16 + jj;
        float g[8];
        {
            float4 g0 = *(const float4*)&gallery[(size_t)j * FEAT + f0];
            float4 g1 = *(const float4*)&gallery[(size_t)j * FEAT + f0 + 4];
            g[0] = g0.x; g[1] = g0.y; g[2] = g0.z; g[3] = g0.w;
            g[4] = g1.x; g[5] = g1.y; g[6] = g1.z; g[7] = g1.w;
        }
        #pragma unroll
        for (int ii = 0; ii < 8; ii++) {
            __half h[8];
            #pragma unroll
            for (int k = 0; k < 8; k++) {
                float d = p[ii][k] - g[k];
                h[k] = __float2half_rn(d * d);
            }
            const int row = (pc * 8 + ii) * NGALLERY + j;
            *(uint4*)&g_A16[(size_t)row * FEAT + f0] = *(uint4*)h;
        }
    }
}

// ---------------- kernel 1a: partial moments (80 blocks) ----------------
__global__ void stats_part_kernel(const float* __restrict__ probe,
                                  const float* __restrict__ gallery) {
    const int f = blockIdx.x * 256 + threadIdx.x;
    const int y = blockIdx.y;
    const float* src = (y < 2) ? probe : gallery;
    const int r0 = (y < 2) ? y * 32 : (y - 2) * 32;
    float s1 = 0.f, s2 = 0.f, s3 = 0.f, s4 = 0.f;
    #pragma unroll 8
    for (int r = 0; r < 32; r++) {
        float v = src[(size_t)(r0 + r) * FEAT + f];
        float v2 = v * v;
        s1 += v; s2 += v2; s3 += v2 * v; s4 += v2 * v2;
    }
    g_part[(y * 4 + 0) * FEAT + f] = s1;
    g_part[(y * 4 + 1) * FEAT + f] = s2;
    g_part[(y * 4 + 2) * FEAT + f] = s3;
    g_part[(y * 4 + 3) * FEAT + f] = s4;
}

// ---------------- kernel 1b: finalize BN stats ----------------
__global__ void stats_final_kernel(const float* __restrict__ gamma) {
    const int f = blockIdx.x * 256 + threadIdx.x;
    float sp1 = 0.f, sp2 = 0.f, sp3 = 0.f, sp4 = 0.f;
    float sg1 = 0.f, sg2 = 0.f, sg3 = 0.f, sg4 = 0.f;
    #pragma unroll
    for (int y = 0; y < 2; y++) {
        sp1 += g_part[(y * 4 + 0) * FEAT + f];
        sp2 += g_part[(y * 4 + 1) * FEAT + f];
        sp3 += g_part[(y * 4 + 2) * FEAT + f];
        sp4 += g_part[(y * 4 + 3) * FEAT + f];
    }
    #pragma unroll
    for (int y = 2; y < 10; y++) {
        sg1 += g_part[(y * 4 + 0) * FEAT + f];
        sg2 += g_part[(y * 4 + 1) * FEAT + f];
        sg3 += g_part[(y * 4 + 2) * FEAT + f];
        sg4 += g_part[(y * 4 + 3) * FEAT + f];
    }
    const float ip = 1.f / NPROBE, ig = 1.f / NGALLERY;
    float mp1 = sp1 * ip, mp2 = sp2 * ip, mp3 = sp3 * ip, mp4 = sp4 * ip;
    float mg1 = sg1 * ig, mg2 = sg2 * ig, mg3 = sg3 * ig, mg4 = sg4 * ig;
    // exact identities: the BN batch is the full (i,j) cartesian product
    float mean = mp2 + mg2 - 2.f * mp1 * mg1;
    float ed2  = mp4 - 4.f * mp3 * mg1 + 6.f * mp2 * mg2 - 4.f * mp1 * mg3 + mg4;
    float var  = ed2 - mean * mean;
    g_mean[f]  = mean;
    g_scale[f] = gamma[f] * rsqrtf(var + BN_EPS);
}

// ---------------- kernel 2: W prep + cconst (mean folded here) ------------
__global__ void wprep_kernel(const float* __restrict__ W,
                             const float* __restrict__ beta,
                             const float* __restrict__ bias) {
    const int c = blockIdx.x;         // 0..767
    const int tid = threadIdx.x;
    const int f0 = tid * 8;
    float acc = 0.f;
    float w[8];
    if (c < NCLS) {
        float4 w0 = *(const float4*)&W[(size_t)c * FEAT + f0];
        float4 w1 = *(const float4*)&W[(size_t)c * FEAT + f0 + 4];
        w[0] = w0.x; w[1] = w0.y; w[2] = w0.z; w[3] = w0.w;
        w[4] = w1.x; w[5] = w1.y; w[6] = w1.z; w[7] = w1.w;
    } else {
        #pragma unroll
        for (int k = 0; k < 8; k++) w[k] = 0.f;
    }
    __half h[8];
    #pragma unroll
    for (int k = 0; k < 8; k++) {
        float s = g_scale[f0 + k];
        h[k] = __float2half_rn(w[k] * s * WSCALE);
        // uncentered A16: cconst absorbs beta - mean*scale
        acc += w[k] * (beta[f0 + k] - g_mean[f0 + k] * s);
    }
    *(uint4*)&g_W16[(size_t)c * FEAT + f0] = *(uint4*)h;
    #pragma unroll
    for (int o = 16; o > 0; o >>= 1)
        acc += __shfl_down_sync(0xFFFFFFFFu, acc, o);
    __shared__ float red[8];
    if ((tid & 31) == 0) red[tid >> 5] = acc;
    __syncthreads();
    if (tid == 0) {
        float t = 0.f;
        #pragma unroll
        for (int k = 0; k < 8; k++) t += red[k];
        g_cconst[c] = t + ((c < NCLS) ? bias[c] : 0.f);
    }
}

// ---------------- kernel 3: fp16 HMMA GEMM, 3 CTAs/SM (frozen config) -----
__global__ void __launch_bounds__(THREADS, 3)
gemm_kernel(float* __restrict__ out) {
    extern __shared__ char smem[];
    const uint32_t sb = smem_u32(smem);
    const int tid = threadIdx.x;
    const int lid = tid & 31;
    const int wid = tid >> 5;

    const int ct = blockIdx.x;            // 0..11
    const int rt = blockIdx.y;            // 0..127
    const int n0 = rt * BM;
    const int c0 = ct * BN;

    const int pr = tid >> 3;              // row base 0..31
    const int pu = tid & 7;               // 16B chunk in 128B row

    const int wm = wid >> 1;              // 0..3
    const int wn = wid & 1;               // 0..1
    const int mbase = wm * 32;
    const int nbase = wn * 32;
    const int a_row  = ((lid >> 3) & 1) * 8 + (lid & 7);
    const int a_colb = (lid >> 4) * 16;
    const int b_row  = (lid >> 4) * 8 + (lid & 7);
    const int b_colb = ((lid >> 3) & 1) * 16;

    float acc[2][4][4];
    #pragma unroll
    for (int im = 0; im < 2; im++)
        #pragma unroll
        for (int in = 0; in < 4; in++)
            #pragma unroll
            for (int r = 0; r < 4; r++) acc[im][in][r] = 0.f;

    auto issue = [&](int kt) {
        const uint32_t st = (uint32_t)(kt % NSTAGES) * STAGE_BYTES;
        const int k0 = kt * BK;
        #pragma unroll
        for (int c = 0; c < 4; c++) {
            int row = pr + c * 32;
            cp16(sb + st + sw128(row * 128 + pu * 16),
                 &g_A16[(size_t)(n0 + row) * FEAT + k0 + pu * 8]);
        }
        #pragma unroll
        for (int c = 0; c < 2; c++) {
            int row = pr + c * 32;
            cp16(sb + st + 16384 + sw128(row * 128 + pu * 16),
                 &g_W16[(size_t)(c0 + row) * FEAT + k0 + pu * 8]);
        }
    };

    issue(0); CP_COMMIT();
    issue(1); CP_COMMIT();
    issue(2); CP_COMMIT();

    for (int kt = 0; kt < KITERS; kt++) {
        CP_WAIT2();            // stage kt resident (2 newer may pend)
        __syncthreads();

        const uint32_t abuf = sb + (uint32_t)(kt % NSTAGES) * STAGE_BYTES;
        const uint32_t bbuf = abuf + 16384;
        #pragma unroll
        for (int ik = 0; ik < 4; ik++) {
            uint32_t a[2][4];
            #pragma unroll
            for (int im = 0; im < 2; im++)
                ldsm4(a[im], abuf +
                      sw128((mbase + im * 16 + a_row) * 128 + ik * 32 + a_colb));
            uint32_t b[8];
            #pragma unroll
            for (int nb = 0; nb < 2; nb++)
                ldsm4(&b[nb * 4], bbuf +
                      sw128((nbase + nb * 16 + b_row) * 128 + ik * 32 + b_colb));
            #pragma unroll
            for (int im = 0; im < 2; im++)
                #pragma unroll
                for (int in = 0; in < 4; in++)
                    mma16816(acc[im][in], a[im], &b[in * 2]);
        }

        __syncthreads();       // reads of stage kt done; buffer reusable
        if (kt + 3 < KITERS) issue(kt + 3);
        CP_COMMIT();           // keep group-count invariant near the tail
    }

    // ---- epilogue: restage through smem, coalesced row stores ----
    float* stage = reinterpret_cast<float*>(smem);   // 128 x EPI_STRIDE fp32
    #pragma unroll
    for (int im = 0; im < 2; im++) {
        #pragma unroll
        for (int in = 0; in < 4; in++) {
            const int r = mbase + im * 16 + (lid >> 2);
            const int c = nbase + in * 8 + (lid & 3) * 2;
            stage[r * EPI_STRIDE + c]           = acc[im][in][0] * WSCALE_INV;
            stage[r * EPI_STRIDE + c + 1]       = acc[im][in][1] * WSCALE_INV;
            stage[(r + 8) * EPI_STRIDE + c]     = acc[im][in][2] * WSCALE_INV;
            stage[(r + 8) * EPI_STRIDE + c + 1] = acc[im][in][3] * WSCALE_INV;
        }
    }
    __syncthreads();
    const int col = c0 + (tid & 63);
    const int rbase = (tid >> 6) * 32;          // 0,32,64,96
    if (col < NCLS) {
        const float cc = g_cconst[col];
        #pragma unroll 8
        for (int r = 0; r < 32; r++)
            out[(size_t)(n0 + rbase + r) * NCLS + col] =
                stage[(rbase + r) * EPI_STRIDE + (tid & 63)] + cc;
    }
}

// ---------------- launch: fork-join two-stream graph ----------------
extern "C" void kernel_launch(void* const* d_in, const int* in_sizes, int n_in,
                              void* d_out, int out_size) {
    const float* probe   = (const float*)d_in[0];
    const float* gallery = (const float*)d_in[1];
    const float* gamma   = (const float*)d_in[2];
    const float* beta    = (const float*)d_in[3];
    const float* W       = (const float*)d_in[4];
    const float* bias    = (const float*)d_in[5];
    float* out = (float*)d_out;

    static cudaStream_t side = nullptr;
    static cudaEvent_t ev_fork = nullptr, ev_join = nullptr;
    static bool init_done = false;
    if (!init_done) {
        cudaStreamCreateWithFlags(&side, cudaStreamNonBlocking);
        cudaEventCreateWithFlags(&ev_fork, cudaEventDisableTiming);
        cudaEventCreateWithFlags(&ev_join, cudaEventDisableTiming);
        cudaFuncSetAttribute(gemm_kernel,
                             cudaFuncAttributeMaxDynamicSharedMemorySize, SMEM_TOTAL);
        init_done = true;
    }

    // fork: A16 build (no dependencies) runs on side stream,
    // concurrent with the stats -> wprep chain on the main stream
    cudaEventRecord(ev_fork, 0);
    cudaStreamWaitEvent(side, ev_fork, 0);
    a16_kernel<<<128, 256, 0, side>>>(probe, gallery);
    cudaEventRecord(ev_join, side);

    stats_part_kernel<<<dim3(8, 10), 256>>>(probe, gallery);
    stats_final_kernel<<<8, 256>>>(gamma);
    wprep_kernel<<<NPAD, 256>>>(W, beta, bias);

    // join: gemm needs both A16 and W16/cconst
    cudaStreamWaitEvent(0, ev_join, 0);
    gemm_kernel<<<dim3(12, 128, 1), THREADS, SMEM_TOTAL>>>(out);
}